// round 5
// baseline (speedup 1.0000x reference)
#include <cuda_runtime.h>
#include <cstdint>

#define Bsz 4096
#define Hd  512
#define G4  2048
#define Av  64
#define Tlen 16
#define PADTOK 64
#define BOSTOK 65

// ---------------- scratch (static device globals; no allocation) ----------------
__device__ __align__(16) float g_h[Bsz * Hd];
__device__ __align__(16) float g_c[Bsz * Hd];
__device__ __align__(16) float g_ipt[Bsz * Hd];
__device__ __align__(16) float g_gates[Bsz * G4];
__device__ __align__(16) float g_logits[Bsz * Av];
__device__ int   g_action[Tlen * Bsz];
__device__ float g_lp[Tlen * Bsz];
__device__ float g_ent[Tlen * Bsz];
__device__ unsigned char g_stopped[Bsz];

// ---------------- threefry2x32 (JAX-compatible, 20 rounds) ----------------
__host__ __device__ inline void tf2x32(uint32_t k0, uint32_t k1,
                                       uint32_t x0, uint32_t x1,
                                       uint32_t &o0, uint32_t &o1) {
    uint32_t ks2 = k0 ^ k1 ^ 0x1BD11BDAu;
    x0 += k0; x1 += k1;
#define RL(v, r) (((v) << (r)) | ((v) >> (32 - (r))))
#define R4(a,b,c,d) \
    x0 += x1; x1 = RL(x1, a); x1 ^= x0; \
    x0 += x1; x1 = RL(x1, b); x1 ^= x0; \
    x0 += x1; x1 = RL(x1, c); x1 ^= x0; \
    x0 += x1; x1 = RL(x1, d); x1 ^= x0;
    R4(13, 15, 26, 6)  x0 += k1;  x1 += ks2 + 1u;
    R4(17, 29, 16, 24) x0 += ks2; x1 += k0 + 2u;
    R4(13, 15, 26, 6)  x0 += k0;  x1 += k1 + 3u;
    R4(17, 29, 16, 24) x0 += k1;  x1 += ks2 + 4u;
    R4(13, 15, 26, 6)  x0 += ks2; x1 += k0 + 5u;
#undef R4
#undef RL
    o0 = x0; o1 = x1;
}

// Partitionable threefry 32-bit random bits for flat element j:
// bits = o0 ^ o1 of threefry(key, (0, j)). Then JAX uniform->gumbel.
__device__ inline float gumbel_from(uint32_t k0, uint32_t k1, uint32_t j) {
    uint32_t o0, o1;
    tf2x32(k0, k1, 0u, j, o0, o1);
    uint32_t bits = o0 ^ o1;
    float u = __uint_as_float((bits >> 9) | 0x3f800000u) - 1.0f;
    const float TINY = 1.1754943508222875e-38f;
    u = u * (1.0f - TINY) + TINY;
    u = fmaxf(TINY, u);
    return -logf(-logf(u));
}

// ---------------- init ----------------
__global__ void k_init(const float* __restrict__ encoded,
                       const float* __restrict__ emb) {
    int idx = blockIdx.x * blockDim.x + threadIdx.x;
    if (idx < Bsz * Hd) {
        float e = encoded[idx];
        g_h[idx] = e;
        g_c[idx] = e;
        g_ipt[idx] = emb[BOSTOK * Hd + (idx & (Hd - 1))];
    }
    if (idx < Bsz) g_stopped[idx] = 0;
}

// ---------------- gates GEMM: gates = [ipt|h] @ [Wih|Whh]^T + bih + bhh ----------------
// M=4096, N=2048, K_virtual=1024. BM=BN=128, BK=8, 256 thr, 8x8 per thread.
// Double-buffered smem: one __syncthreads per K-iteration.
__global__ __launch_bounds__(256, 2) void k_gates(const float* __restrict__ Wih,
                                                  const float* __restrict__ Whh,
                                                  const float* __restrict__ bih,
                                                  const float* __restrict__ bhh) {
    __shared__ float As[2][8][128];
    __shared__ float Bs[2][8][128];
    const int bm = blockIdx.y * 128;
    const int bn = blockIdx.x * 128;
    const int t  = threadIdx.x;
    const int tx = t & 15;        // 0..15 (cols)
    const int ty = t >> 4;        // 0..15 (rows)
    const int lr = t >> 1;        // 0..127 load row
    const int lk = (t & 1) * 4;   // 0 or 4

    float acc[8][8];
#pragma unroll
    for (int i = 0; i < 8; i++)
#pragma unroll
        for (int j = 0; j < 8; j++) acc[i][j] = 0.f;

    float4 av, bv;
    {   // prologue: load tile 0 into buffer 0
        const float* Ap = g_ipt;
        const float* Bp = Wih;
        av = *(const float4*)(Ap + (size_t)(bm + lr) * 512 + lk);
        bv = *(const float4*)(Bp + (size_t)(bn + lr) * 512 + lk);
        As[0][lk + 0][lr] = av.x; As[0][lk + 1][lr] = av.y;
        As[0][lk + 2][lr] = av.z; As[0][lk + 3][lr] = av.w;
        Bs[0][lk + 0][lr] = bv.x; Bs[0][lk + 1][lr] = bv.y;
        Bs[0][lk + 2][lr] = bv.z; Bs[0][lk + 3][lr] = bv.w;
    }
    __syncthreads();

    for (int it = 0; it < 128; it++) {
        const int cur = it & 1;
        if (it + 1 < 128) {
            const int k0 = (it + 1) * 8;
            const float* Ap = (k0 < 512) ? g_ipt : g_h;
            const float* Bp = (k0 < 512) ? Wih : Whh;
            const int ka = (k0 & 511) + lk;
            av = *(const float4*)(Ap + (size_t)(bm + lr) * 512 + ka);
            bv = *(const float4*)(Bp + (size_t)(bn + lr) * 512 + ka);
        }
#pragma unroll
        for (int kk = 0; kk < 8; kk++) {
            float ar[8], br[8];
#pragma unroll
            for (int i = 0; i < 4; i++) {
                ar[i]     = As[cur][kk][ty * 4 + i];
                ar[4 + i] = As[cur][kk][64 + ty * 4 + i];
            }
#pragma unroll
            for (int j = 0; j < 4; j++) {
                br[j]     = Bs[cur][kk][tx * 4 + j];
                br[4 + j] = Bs[cur][kk][64 + tx * 4 + j];
            }
#pragma unroll
            for (int i = 0; i < 8; i++)
#pragma unroll
                for (int j = 0; j < 8; j++)
                    acc[i][j] = fmaf(ar[i], br[j], acc[i][j]);
        }
        if (it + 1 < 128) {
            const int nxt = cur ^ 1;
            As[nxt][lk + 0][lr] = av.x; As[nxt][lk + 1][lr] = av.y;
            As[nxt][lk + 2][lr] = av.z; As[nxt][lk + 3][lr] = av.w;
            Bs[nxt][lk + 0][lr] = bv.x; Bs[nxt][lk + 1][lr] = bv.y;
            Bs[nxt][lk + 2][lr] = bv.z; Bs[nxt][lk + 3][lr] = bv.w;
            __syncthreads();
        }
    }
#pragma unroll
    for (int i = 0; i < 8; i++) {
        int r = bm + ((i < 4) ? (ty * 4 + i) : (64 + ty * 4 + i - 4));
#pragma unroll
        for (int j = 0; j < 8; j++) {
            int c = bn + ((j < 4) ? (tx * 4 + j) : (64 + tx * 4 + j - 4));
            g_gates[(size_t)r * G4 + c] = acc[i][j] + bih[c] + bhh[c];
        }
    }
}

// ---------------- LSTM pointwise ----------------
__global__ void k_lstm() {
    int idx = blockIdx.x * blockDim.x + threadIdx.x;
    int m = idx >> 9, jj = idx & 511;
    const float* gr = g_gates + (size_t)m * G4 + jj;
    float gi = gr[0], gf = gr[512], gg = gr[1024], go = gr[1536];
    float si = 1.f / (1.f + expf(-gi));
    float sf = 1.f / (1.f + expf(-gf));
    float so = 1.f / (1.f + expf(-go));
    float c = sf * g_c[idx] + si * tanhf(gg);
    g_c[idx] = c;
    g_h[idx] = so * tanhf(c);
}

// ---------------- logits GEMM: logits = h @ Wp^T + bp ----------------
// 32 rows x 64 cols per block, 256 threads, K-chunks of 64.
__global__ __launch_bounds__(256) void k_logits(const float* __restrict__ Wp,
                                                const float* __restrict__ bp) {
    __shared__ float As[32][64];
    __shared__ float Bs[64][65];
    const int r0 = blockIdx.x * 32;
    const int t = threadIdx.x;
    const int col = t & 63;
    const int rb = (t >> 6) * 8;
    float acc[8] = {0, 0, 0, 0, 0, 0, 0, 0};

    for (int k0 = 0; k0 < 512; k0 += 64) {
        int arow = t >> 3, akk = (t & 7) * 8;
        float4 a0 = *(const float4*)(g_h + (size_t)(r0 + arow) * 512 + k0 + akk);
        float4 a1 = *(const float4*)(g_h + (size_t)(r0 + arow) * 512 + k0 + akk + 4);
        int brow = t >> 2, bkk = (t & 3) * 16;
        float4 w0 = *(const float4*)(Wp + (size_t)brow * 512 + k0 + bkk);
        float4 w1 = *(const float4*)(Wp + (size_t)brow * 512 + k0 + bkk + 4);
        float4 w2 = *(const float4*)(Wp + (size_t)brow * 512 + k0 + bkk + 8);
        float4 w3 = *(const float4*)(Wp + (size_t)brow * 512 + k0 + bkk + 12);
        __syncthreads();
        *(float4*)&As[arow][akk] = a0;
        *(float4*)&As[arow][akk + 4] = a1;
        Bs[brow][bkk + 0] = w0.x;  Bs[brow][bkk + 1] = w0.y;
        Bs[brow][bkk + 2] = w0.z;  Bs[brow][bkk + 3] = w0.w;
        Bs[brow][bkk + 4] = w1.x;  Bs[brow][bkk + 5] = w1.y;
        Bs[brow][bkk + 6] = w1.z;  Bs[brow][bkk + 7] = w1.w;
        Bs[brow][bkk + 8] = w2.x;  Bs[brow][bkk + 9] = w2.y;
        Bs[brow][bkk + 10] = w2.z; Bs[brow][bkk + 11] = w2.w;
        Bs[brow][bkk + 12] = w3.x; Bs[brow][bkk + 13] = w3.y;
        Bs[brow][bkk + 14] = w3.z; Bs[brow][bkk + 15] = w3.w;
        __syncthreads();
#pragma unroll
        for (int k4 = 0; k4 < 16; k4++) {
            float b0 = Bs[col][k4 * 4 + 0];
            float b1 = Bs[col][k4 * 4 + 1];
            float b2 = Bs[col][k4 * 4 + 2];
            float b3 = Bs[col][k4 * 4 + 3];
#pragma unroll
            for (int r = 0; r < 8; r++) {
                float4 a = *(const float4*)&As[rb + r][k4 * 4];
                acc[r] = fmaf(a.x, b0, fmaf(a.y, b1, fmaf(a.z, b2, fmaf(a.w, b3, acc[r]))));
            }
        }
    }
#pragma unroll
    for (int r = 0; r < 8; r++)
        g_logits[(size_t)(r0 + rb + r) * 64 + col] = acc[r] + bp[col];
}

// ---------------- sampling: log_softmax + gumbel argmax + state update ----------------
__global__ void k_sample(const float* __restrict__ emb, int step,
                         uint32_t key0, uint32_t key1) {
    const int b = blockIdx.x;
    const int lane = threadIdx.x;  // 32 threads/block
    float l0 = g_logits[(size_t)b * 64 + lane];
    float l1 = g_logits[(size_t)b * 64 + 32 + lane];

    float m = fmaxf(l0, l1);
#pragma unroll
    for (int off = 16; off > 0; off >>= 1)
        m = fmaxf(m, __shfl_xor_sync(0xffffffffu, m, off));
    float sh0 = l0 - m, sh1 = l1 - m;
    float s = expf(sh0) + expf(sh1);
#pragma unroll
    for (int off = 16; off > 0; off >>= 1)
        s += __shfl_xor_sync(0xffffffffu, s, off);
    float ls = logf(s);
    float lp0 = sh0 - ls, lp1 = sh1 - ls;
    float ent = expf(lp0) * (-lp0) + expf(lp1) * (-lp1);
#pragma unroll
    for (int off = 16; off > 0; off >>= 1)
        ent += __shfl_xor_sync(0xffffffffu, ent, off);

    float z0 = l0 + gumbel_from(key0, key1, (uint32_t)(b * 64 + lane));
    float z1 = l1 + gumbel_from(key0, key1, (uint32_t)(b * 64 + 32 + lane));
    float zb; int ib;
    if (z1 > z0) { zb = z1; ib = lane + 32; } else { zb = z0; ib = lane; }
#pragma unroll
    for (int off = 16; off > 0; off >>= 1) {
        float oz = __shfl_xor_sync(0xffffffffu, zb, off);
        int   oi = __shfl_xor_sync(0xffffffffu, ib, off);
        if (oz > zb || (oz == zb && oi < ib)) { zb = oz; ib = oi; }
    }

    float cand = (ib < 32) ? lp0 : lp1;
    float lp_sel = __shfl_sync(0xffffffffu, cand, ib & 31);
    unsigned char st = g_stopped[b];
    __syncwarp();
    int act = st ? PADTOK : ib;
    if (lane == 0) {
        float live = st ? 0.f : 1.f;
        g_action[step * Bsz + b] = act;
        g_lp[step * Bsz + b] = lp_sel * live;
        g_ent[step * Bsz + b] = ent * live;
        if (!st && ib == 0) g_stopped[b] = 1;
    }
    const float* er = emb + (size_t)act * Hd;
    float* ir = g_ipt + (size_t)b * Hd;
#pragma unroll
    for (int kk = lane * 4; kk < Hd; kk += 128)
        *(float4*)(ir + kk) = *(const float4*)(er + kk);
}

// ---------------- final pack: msg | msg_len | lp | ent_avg (float32) ----------------
__global__ void k_pack(float* __restrict__ out) {
    int b = blockIdx.x * blockDim.x + threadIdx.x;
    if (b >= Bsz) return;
    int len = 0;
    float esum = 0.f;
#pragma unroll
    for (int t = 0; t < Tlen; t++) {
        int a = g_action[t * Bsz + b];
        out[(size_t)b * Tlen + t] = (float)a;
        if (a != PADTOK) len++;
        out[(size_t)Bsz * Tlen + Bsz + (size_t)b * Tlen + t] = g_lp[t * Bsz + b];
        esum += g_ent[t * Bsz + b];
    }
    out[(size_t)Bsz * Tlen + b] = (float)len;
    out[2 * (size_t)Bsz * Tlen + Bsz + b] = esum / (float)len;
}

extern "C" void kernel_launch(void* const* d_in, const int* in_sizes, int n_in,
                              void* d_out, int out_size) {
    const float* encoded = (const float*)d_in[0];
    const float* emb     = (const float*)d_in[1];
    const float* Wih     = (const float*)d_in[2];
    const float* Whh     = (const float*)d_in[3];
    const float* bih     = (const float*)d_in[4];
    const float* bhh     = (const float*)d_in[5];
    const float* Wp      = (const float*)d_in[6];
    const float* bp      = (const float*)d_in[7];
    float* out = (float*)d_out;

    // JAX fold-like split (partitionable threefry): key_t = threefry(key(42), (0, t))
    uint32_t k0s[Tlen], k1s[Tlen];
    for (int t = 0; t < Tlen; t++)
        tf2x32(0u, 42u, 0u, (uint32_t)t, k0s[t], k1s[t]);

    k_init<<<(Bsz * Hd + 255) / 256, 256>>>(encoded, emb);
    for (int t = 0; t < Tlen; t++) {
        k_gates<<<dim3(G4 / 128, Bsz / 128), 256>>>(Wih, Whh, bih, bhh);
        k_lstm<<<(Bsz * Hd) / 256, 256>>>();
        k_logits<<<Bsz / 32, 256>>>(Wp, bp);
        k_sample<<<Bsz, 32>>>(emb, t, k0s[t], k1s[t]);
    }
    k_pack<<<(Bsz + 255) / 256, 256>>>(out);
}